// round 14
// baseline (speedup 1.0000x reference)
#include <cuda_runtime.h>
#include <math.h>

#define SR_F        24000.0f
#define INV_SR_F    (1.0f / 24000.0f)
#define TWO_PI_F    6.2831855f
#define PI_F        3.1415927f
#define HALF_STATIC 1200
#define MAX_SAMPLES 240000
#define HALF_LOG2E  0.7213475204444817f
#define MAX_ATOMS   16384
#define TILE        256
#define TILE_SHIFT  8
#define NTILES      938              /* ceil(240000/256) */
#define RB_THREADS  64               /* 64 threads x 4 samples = 256 tile */
#define MAX_LIST    262144

// t[idx] = div.full.f32(idx, 24000) — bit-identical to the reference's t.
__device__ __align__(16) float g_t_table[MAX_SAMPLES];
__device__ int   g_tile_count[NTILES];
__device__ int   g_tile_start[NTILES];
__device__ int   g_tile_fill[NTILES];
__device__ __align__(16) float4 g_pA[MAX_ATOMS];   // tau, om_w, g_w, ph2
__device__ __align__(8)  float2 g_pB[MAX_ATOMS];   // envc, l2a
__device__ int2  g_range[MAX_ATOMS];               // [tLo, tHi] tile range
__device__ __align__(16) float4 g_lpA[MAX_LIST];   // per-tile packed params
__device__ __align__(8)  float2 g_lpB[MAX_LIST];

__device__ __forceinline__ float div_full(float a, float b) {
    float r; asm("div.full.f32 %0, %1, %2;" : "=f"(r) : "f"(a), "f"(b)); return r;
}
__device__ __forceinline__ float ex2_approx(float x) {
    float r; asm("ex2.approx.f32 %0, %1;" : "=f"(r) : "f"(x)); return r;
}
__device__ __forceinline__ float cos_approx(float x) {
    float r; asm("cos.approx.f32 %0, %1;" : "=f"(r) : "f"(x)); return r;
}

// 1) t-table + zero tile histogram. (No output zeroing: gather writes all.)
__global__ void init_kernel(int n4) {
    int i = blockIdx.x * blockDim.x + threadIdx.x;
    if (i < n4) {
        int b = i * 4;
        float4 tv;
        tv.x = div_full((float)(b    ), SR_F);
        tv.y = div_full((float)(b + 1), SR_F);
        tv.z = div_full((float)(b + 2), SR_F);
        tv.w = div_full((float)(b + 3), SR_F);
        reinterpret_cast<float4*>(g_t_table)[i] = tv;
    }
    if (i < NTILES) g_tile_count[i] = 0;
}

// 2) Per-atom derived params + window -> tile range + histogram.
__global__ void prep_kernel(const float* __restrict__ amplitude,
                            const float* __restrict__ tau,
                            const float* __restrict__ omega,
                            const float* __restrict__ sigma,
                            const float* __restrict__ phi,
                            const float* __restrict__ gamma,
                            int num_atoms, int num_samples) {
    int atom = blockIdx.x * blockDim.x + threadIdx.x;
    if (atom >= num_atoms) return;

    const float a  = amplitude[atom];
    const float tu = tau[atom];
    const float om = omega[atom];
    const float sg = sigma[atom];
    const float ph = phi[atom];
    const float gm = gamma[atom];

    const int   c    = __float2int_rn(__fmul_rn(tu, SR_F));  // jnp.round match
    const float r    = __fmul_rn(5.0f, sg);
    const float om_w = __fmul_rn(TWO_PI_F, om);
    const float g_w  = __fmul_rn(PI_F, gm);
    const float inv_sg = __frcp_rn(sg);
    const float envc   = -__fmul_rn(HALF_LOG2E, __fmul_rn(inv_sg, inv_sg));
    const float l2a    = __log2f(fabsf(a));
    const float ph2    = (a < 0.0f) ? __fadd_rn(ph, PI_F) : ph;

    const float delta0 = fmaf((float)c, INV_SR_F, -tu);
    int jlo = (int)ceilf ((-r - delta0) * SR_F) - 2;
    int jhi = (int)floorf(( r - delta0) * SR_F) + 2;
    jlo = max(jlo, max(-HALF_STATIC, -c));
    jhi = min(jhi, min( HALF_STATIC, num_samples - 1 - c));
    if (jlo > jhi) { g_range[atom] = make_int2(1, 0); return; }

    const int tLo = (c + jlo) >> TILE_SHIFT;   // c+jlo >= 0
    const int tHi = (c + jhi) >> TILE_SHIFT;   // c+jhi <= num_samples-1
    g_pA[atom]   = make_float4(tu, om_w, g_w, ph2);
    g_pB[atom]   = make_float2(envc, l2a);
    g_range[atom] = make_int2(tLo, tHi);
    for (int t = tLo; t <= tHi; ++t) atomicAdd(&g_tile_count[t], 1);
}

// 3) Exclusive prefix sum over NTILES (single 1024-thread block).
__global__ void scan_kernel() {
    __shared__ int s[1024];
    int tid = threadIdx.x;
    int v = (tid < NTILES) ? g_tile_count[tid] : 0;
    s[tid] = v;
    __syncthreads();
    for (int off = 1; off < 1024; off <<= 1) {
        int x = (tid >= off) ? s[tid - off] : 0;
        __syncthreads();
        s[tid] += x;
        __syncthreads();
    }
    if (tid < NTILES) {
        int ex = s[tid] - v;
        g_tile_start[tid] = ex;
        g_tile_fill[tid]  = ex;
    }
}

// 4) Write packed params into each overlapped tile's list segment.
__global__ void fill_kernel(int num_atoms) {
    int atom = blockIdx.x * blockDim.x + threadIdx.x;
    if (atom >= num_atoms) return;
    int2 rg = g_range[atom];
    if (rg.x > rg.y) return;
    float4 pa = g_pA[atom];
    float2 pb = g_pB[atom];
    for (int t = rg.x; t <= rg.y; ++t) {
        int pos = atomicAdd(&g_tile_fill[t], 1);
        g_lpA[pos] = pa;
        g_lpB[pos] = pb;
    }
}

// 5) GATHER: one block per 256-sample tile, 4 samples per thread in
// registers; loop the tile's atom list (streaming LDG.128), accumulate,
// one coalesced float4 store. No atomics, no table re-reads: the L2/LTS
// bandwidth wall (~260MB -> ~5MB) is gone.
__global__ __launch_bounds__(RB_THREADS)
void render_kernel(float* __restrict__ out, int num_samples) {
    const int tile = blockIdx.x;
    const int s0   = tile * TILE + 4 * (int)threadIdx.x;
    if (s0 >= num_samples) return;                 // tail tile guard

    const float4 tv = *reinterpret_cast<const float4*>(g_t_table + s0);
    int k       = g_tile_start[tile];
    const int e = k + g_tile_count[tile];
    float4 acc = make_float4(0.f, 0.f, 0.f, 0.f);

    for (; k < e; ++k) {
        const float4 pa = __ldg(&g_lpA[k]);        // tau, om_w, g_w, ph2
        const float2 pb = __ldg(&g_lpB[k]);        // envc, l2a
        {
            const float dt  = __fadd_rn(tv.x, -pa.x);
            const float dt2 = __fmul_rn(dt, dt);
            const float env = ex2_approx(fmaf(pb.x, dt2, pb.y));
            const float phs = fmaf(pa.y, dt, fmaf(pa.z, dt2, pa.w));
            acc.x = fmaf(env, cos_approx(phs), acc.x);
        }
        {
            const float dt  = __fadd_rn(tv.y, -pa.x);
            const float dt2 = __fmul_rn(dt, dt);
            const float env = ex2_approx(fmaf(pb.x, dt2, pb.y));
            const float phs = fmaf(pa.y, dt, fmaf(pa.z, dt2, pa.w));
            acc.y = fmaf(env, cos_approx(phs), acc.y);
        }
        {
            const float dt  = __fadd_rn(tv.z, -pa.x);
            const float dt2 = __fmul_rn(dt, dt);
            const float env = ex2_approx(fmaf(pb.x, dt2, pb.y));
            const float phs = fmaf(pa.y, dt, fmaf(pa.z, dt2, pa.w));
            acc.z = fmaf(env, cos_approx(phs), acc.z);
        }
        {
            const float dt  = __fadd_rn(tv.w, -pa.x);
            const float dt2 = __fmul_rn(dt, dt);
            const float env = ex2_approx(fmaf(pb.x, dt2, pb.y));
            const float phs = fmaf(pa.y, dt, fmaf(pa.z, dt2, pa.w));
            acc.w = fmaf(env, cos_approx(phs), acc.w);
        }
    }
    *reinterpret_cast<float4*>(out + s0) = acc;
}

extern "C" void kernel_launch(void* const* d_in, const int* in_sizes, int n_in,
                              void* d_out, int out_size) {
    const float* amplitude = (const float*)d_in[0];
    const float* tau       = (const float*)d_in[1];
    const float* omega     = (const float*)d_in[2];
    const float* sigma     = (const float*)d_in[3];
    const float* phi       = (const float*)d_in[4];
    const float* gamma     = (const float*)d_in[5];
    float* out = (float*)d_out;

    const int num_atoms   = in_sizes[0];     // 16384
    const int num_samples = out_size;        // 240000
    const int n4 = num_samples / 4;

    init_kernel<<<(n4 + 255) / 256, 256>>>(n4);
    prep_kernel<<<(num_atoms + 127) / 128, 128>>>(
        amplitude, tau, omega, sigma, phi, gamma, num_atoms, num_samples);
    scan_kernel<<<1, 1024>>>();
    fill_kernel<<<(num_atoms + 127) / 128, 128>>>(num_atoms);
    render_kernel<<<NTILES, RB_THREADS>>>(out, num_samples);
}

// round 15
// speedup vs baseline: 1.3521x; 1.3521x over previous
#include <cuda_runtime.h>
#include <math.h>

#define SR_F        24000.0f
#define INV_SR_F    (1.0f / 24000.0f)
#define TWO_PI_F    6.2831855f
#define PI_F        3.1415927f
#define HALF_STATIC 1200
#define HALF_LOG2E  0.7213475204444817f
#define MAX_ATOMS   16384
#define TILE        256
#define TILE_SHIFT  8
#define NTILES      938              /* ceil(240000/256) */
#define SAMPLES_PAD (NTILES * TILE)  /* 240128 */
#define RT          128              /* render threads: 128 x 2 samples */
#define LIST_CAP    4096

// t[idx] = div.full.f32(idx, 24000) — bit-identical to the reference's t.
__device__ __align__(16) float g_t_table[SAMPLES_PAD];
__device__ __align__(16) float4 g_pA[MAX_ATOMS];   // tau, om_w, g_w, ph2
__device__ __align__(8)  float2 g_pB[MAX_ATOMS];   // envc, l2a
__device__ int g_rangep[MAX_ATOMS];                // tLo | (tHi << 16)

__device__ __forceinline__ float div_full(float a, float b) {
    float r; asm("div.full.f32 %0, %1, %2;" : "=f"(r) : "f"(a), "f"(b)); return r;
}
__device__ __forceinline__ float ex2_approx(float x) {
    float r; asm("ex2.approx.f32 %0, %1;" : "=f"(r) : "f"(x)); return r;
}
__device__ __forceinline__ float cos_approx(float x) {
    float r; asm("cos.approx.f32 %0, %1;" : "=f"(r) : "f"(x)); return r;
}

// Merged init: threads [0, SAMPLES_PAD/4) fill the t-table; threads
// [0, num_atoms) also compute per-atom derived params + packed tile range.
__global__ void prep_kernel(const float* __restrict__ amplitude,
                            const float* __restrict__ tau,
                            const float* __restrict__ omega,
                            const float* __restrict__ sigma,
                            const float* __restrict__ phi,
                            const float* __restrict__ gamma,
                            int num_atoms, int num_samples) {
    const int i = blockIdx.x * blockDim.x + threadIdx.x;

    if (i < SAMPLES_PAD / 4) {
        int b = i * 4;
        float4 tv;
        tv.x = div_full((float)(b    ), SR_F);
        tv.y = div_full((float)(b + 1), SR_F);
        tv.z = div_full((float)(b + 2), SR_F);
        tv.w = div_full((float)(b + 3), SR_F);
        reinterpret_cast<float4*>(g_t_table)[i] = tv;
    }

    if (i < num_atoms) {
        const float a  = amplitude[i];
        const float tu = tau[i];
        const float om = omega[i];
        const float sg = sigma[i];
        const float ph = phi[i];
        const float gm = gamma[i];

        const int   c    = __float2int_rn(__fmul_rn(tu, SR_F)); // jnp.round
        const float r    = __fmul_rn(5.0f, sg);
        const float om_w = __fmul_rn(TWO_PI_F, om);
        const float g_w  = __fmul_rn(PI_F, gm);
        const float inv_sg = __frcp_rn(sg);
        const float envc   = -__fmul_rn(HALF_LOG2E, __fmul_rn(inv_sg, inv_sg));
        const float l2a    = __log2f(fabsf(a));
        const float ph2    = (a < 0.0f) ? __fadd_rn(ph, PI_F) : ph;

        const float delta0 = fmaf((float)c, INV_SR_F, -tu);
        int jlo = (int)ceilf ((-r - delta0) * SR_F) - 2;
        int jhi = (int)floorf(( r - delta0) * SR_F) + 2;
        jlo = max(jlo, max(-HALF_STATIC, -c));
        jhi = min(jhi, min( HALF_STATIC, num_samples - 1 - c));

        int pack;
        if (jlo > jhi) {
            pack = 0x7FFF;                         // tLo=32767: never matches
        } else {
            const int tLo = (c + jlo) >> TILE_SHIFT;
            const int tHi = (c + jhi) >> TILE_SHIFT;
            pack = tLo | (tHi << 16);
        }
        g_pA[i]     = make_float4(tu, om_w, g_w, ph2);
        g_pB[i]     = make_float2(envc, l2a);
        g_rangep[i] = pack;
    }
}

__device__ __forceinline__ void eval2(float2& acc, float2 tv,
                                      float4 pa, float2 pb) {
    {
        const float dt  = __fadd_rn(tv.x, -pa.x);
        const float dt2 = __fmul_rn(dt, dt);
        const float env = ex2_approx(fmaf(pb.x, dt2, pb.y));
        const float phs = fmaf(pa.y, dt, fmaf(pa.z, dt2, pa.w));
        acc.x = fmaf(env, cos_approx(phs), acc.x);
    }
    {
        const float dt  = __fadd_rn(tv.y, -pa.x);
        const float dt2 = __fmul_rn(dt, dt);
        const float env = ex2_approx(fmaf(pb.x, dt2, pb.y));
        const float phs = fmaf(pa.y, dt, fmaf(pa.z, dt2, pa.w));
        acc.y = fmaf(env, cos_approx(phs), acc.y);
    }
}

// GATHER, self-binning: one block per 256-sample tile. Phase 1: all threads
// scan the packed tile-range array (L1-resident, 64KB) and ballot-compact
// overlapping atom indices into shared memory. Phase 2: loop the compacted
// list, accumulate 2 samples/thread in registers, one coalesced float2 store.
// No global atomics, no materialized lists — L2 traffic ~10MB total.
__global__ __launch_bounds__(RT)
void render_kernel(float* __restrict__ out, int num_atoms, int num_samples) {
    const int tile = blockIdx.x;
    const int tid  = (int)threadIdx.x;
    const int s0   = tile * TILE + 2 * tid;

    __shared__ int s_list[LIST_CAP];
    __shared__ int s_cnt;
    if (tid == 0) s_cnt = 0;
    __syncthreads();

    // Phase 1: scan + compact.
    const unsigned full = 0xFFFFFFFFu;
    const int lane = tid & 31;
    for (int base = 0; base < num_atoms; base += RT) {
        const int  i   = base + tid;            // num_atoms % RT == 0
        const int  p   = g_rangep[i];
        const bool hit = (tile >= (p & 0xFFFF)) && (tile <= (p >> 16));
        const unsigned m = __ballot_sync(full, hit);
        int wb = 0;
        if (lane == 0 && m) wb = atomicAdd(&s_cnt, __popc(m));
        wb = __shfl_sync(full, wb, 0);
        if (hit) s_list[wb + __popc(m & ((1u << lane) - 1u))] = i;
    }
    __syncthreads();
    const int cnt = min(s_cnt, LIST_CAP);

    // Phase 2: evaluate list (unrolled x2 for load MLP).
    const float2 tv = *reinterpret_cast<const float2*>(g_t_table + s0);
    float2 acc = make_float2(0.f, 0.f);
    int k = 0;
    for (; k + 1 < cnt; k += 2) {
        const int i0 = s_list[k];
        const int i1 = s_list[k + 1];
        const float4 pa0 = g_pA[i0];
        const float2 pb0 = g_pB[i0];
        const float4 pa1 = g_pA[i1];
        const float2 pb1 = g_pB[i1];
        eval2(acc, tv, pa0, pb0);
        eval2(acc, tv, pa1, pb1);
    }
    if (k < cnt) {
        const int i0 = s_list[k];
        eval2(acc, tv, g_pA[i0], g_pB[i0]);
    }

    if (s0 < num_samples)                       // tail tile guard (s0 even)
        *reinterpret_cast<float2*>(out + s0) = acc;
}

extern "C" void kernel_launch(void* const* d_in, const int* in_sizes, int n_in,
                              void* d_out, int out_size) {
    const float* amplitude = (const float*)d_in[0];
    const float* tau       = (const float*)d_in[1];
    const float* omega     = (const float*)d_in[2];
    const float* sigma     = (const float*)d_in[3];
    const float* phi       = (const float*)d_in[4];
    const float* gamma     = (const float*)d_in[5];
    float* out = (float*)d_out;

    const int num_atoms   = in_sizes[0];     // 16384
    const int num_samples = out_size;        // 240000

    const int prep_threads = SAMPLES_PAD / 4;   // covers both table & atoms
    prep_kernel<<<(prep_threads + 255) / 256, 256>>>(
        amplitude, tau, omega, sigma, phi, gamma, num_atoms, num_samples);
    render_kernel<<<NTILES, RT>>>(out, num_atoms, num_samples);
}